// round 4
// baseline (speedup 1.0000x reference)
#include <cuda_runtime.h>
#include <math.h>

#define NB 8
#define NC 20
#define NROWS 160
#define NP 8732
#define NM 16
#define THREADS 1024
#define NIT 9                    // ceil(NP/1024)
#define THRESH_BITS 0x3F000000   // bits of 0.5f

// row outputs + completion counter (zero-init; counter self-restored)
__device__ float g_rconf[NROWS], g_rl1[NROWS], g_rnp[NROWS];
__device__ int   g_counter;

// ---- helpers ----
__device__ __forceinline__ float fmax_i(float a, float b) {
    return __int_as_float(max(__float_as_int(a), __float_as_int(b)));
}
__device__ __forceinline__ float fmin_i(float a, float b) {
    return __int_as_float(min(__float_as_int(a), __float_as_int(b)));
}
__device__ __forceinline__ float iou_bp(float4 b, float barea,
                                        float px1, float py1, float px2, float py2,
                                        float parea) {
    float iw = fmin_i(b.z, px2) - fmax_i(b.x, px1);
    float ih = fmin_i(b.w, py2) - fmax_i(b.y, py1);
    iw = fmax_i(iw, 0.f); ih = fmax_i(ih, 0.f);
    float inter = iw * ih;
    return __fdividef(inter, barea + parea - inter);
}
__device__ __forceinline__ float ce_from_scores(float2 sc, int cls) {
    float mx  = fmaxf(sc.x, sc.y);
    float lse = mx + __logf(1.f + __expf(-fabsf(sc.x - sc.y)));
    return lse - (cls ? sc.y : sc.x);
}
__device__ __forceinline__ float l1_term(float4 b, float4 pr, float4 pl) {
    float cx = (b.x + b.z) * 0.5f, cy = (b.y + b.w) * 0.5f;
    float w  = b.z - b.x,          h  = b.w - b.y;
    float gx = __fdividef((cx - pr.x) * 10.f, pr.z);
    float gy = __fdividef((cy - pr.y) * 10.f, pr.w);
    float gw = __logf(__fdividef(w, pr.z)) * 5.f;
    float gh = __logf(__fdividef(h, pr.w)) * 5.f;
    return fabsf(pl.x - gx) + fabsf(pl.y - gy) + fabsf(pl.z - gw) + fabsf(pl.w - gh);
}
__device__ __forceinline__ float warp_sum(float v) {
#pragma unroll
    for (int o = 16; o; o >>= 1) v += __shfl_down_sync(0xffffffffu, v, o);
    return v;
}

__device__ __forceinline__ void select_scan(unsigned* s_hist, unsigned* s_pref, int* s_kk,
                                            unsigned pref, int shift, int lane, int tid)
{
    if (tid < 32) {
        int kk = *s_kk;          // read BEFORE any lane may write
        __syncwarp();
        unsigned h[8]; unsigned lsum = 0;
        const int base = (31 - lane) * 8;   // lane 0 -> bins 248..255
#pragma unroll
        for (int i = 0; i < 8; i++) { h[i] = s_hist[base + i]; lsum += h[i]; }
        unsigned incl = lsum;
#pragma unroll
        for (int off = 1; off < 32; off <<= 1) {
            unsigned v = __shfl_up_sync(0xffffffffu, incl, off);
            if (lane >= off) incl += v;
        }
        unsigned excl = incl - lsum;
        if (excl < (unsigned)kk && incl >= (unsigned)kk) {
            unsigned cum = excl;
#pragma unroll
            for (int i = 7; i >= 0; i--) {
                unsigned cnt = h[i];
                if (cum + cnt >= (unsigned)kk) {
                    *s_pref = pref | ((unsigned)(base + i) << shift);
                    *s_kk   = kk - (int)cum;
                    break;
                }
                cum += cnt;
            }
        }
    }
}

__global__ __launch_bounds__(THREADS, 1) void mb_all(
    const float* __restrict__ ploc, const float* __restrict__ pscore,
    const float* __restrict__ boxes, const int* __restrict__ labels,
    const float* __restrict__ priors, float* __restrict__ out)
{
    __shared__ int      s_ce[NP];       // phase A: packed (iou<<4|m); phase B: ce_neg bits
    __shared__ unsigned s_hist[256];
    __shared__ float4   s_bx4[NM];
    __shared__ float    s_area[NM];
    __shared__ int      s_lab[NM];
    __shared__ unsigned long long s_best[NM];
    __shared__ float    s_wl1[32], s_wcp[32];
    __shared__ int      s_wnp[32];
    __shared__ float    s_sumgt, s_conf, s_l1;
    __shared__ int      s_kk, s_npos, s_fin;
    __shared__ unsigned s_pref;

    const int row = blockIdx.x, tid = threadIdx.x;
    const int lane = tid & 31, wid = tid >> 5;

    if (tid < NM) {
        const float* b = boxes + ((size_t)row * NM + tid) * 4;
        float4 v = make_float4(b[0], b[1], b[2], b[3]);
        s_bx4[tid]  = v;
        s_area[tid] = (v.z - v.x) * (v.w - v.y);
        s_lab[tid]  = labels[(size_t)row * NM + tid];
        s_best[tid] = 0ull;
    }
    if (tid < 256) s_hist[tid] = 0u;
    if (tid == 0)  { s_sumgt = 0.f; s_fin = 0; }
    __syncthreads();

    const float4* __restrict__ prior4 = (const float4*)priors;
    const float2* __restrict__ sc2 = (const float2*)pscore + (size_t)row * NP;
    const float4* __restrict__ pl4 = (const float4*)ploc   + (size_t)row * NP;

    // ---- pass 1: IoU matching, 4 chunks of 4 boxes ----
#pragma unroll 1
    for (int ch = 0; ch < 4; ch++) {
        float4 bb[4]; float ba[4];
#pragma unroll
        for (int i = 0; i < 4; i++) { bb[i] = s_bx4[ch * 4 + i]; ba[i] = s_area[ch * 4 + i]; }
        unsigned bbest[4] = {0u, 0u, 0u, 0u};

#pragma unroll 1
        for (int it = 0; it < NIT; it++) {
            int off = it * THREADS + tid;
            bool act = off < NP;
            int p = act ? off : 0;
            float4 pr = prior4[p];
            float hw = pr.z * 0.5f, hh = pr.w * 0.5f;
            float px1 = pr.x - hw, py1 = pr.y - hh;
            float px2 = pr.x + hw, py2 = pr.y + hh;
            if (!act) { px1 = px2 = py1 = py2 = -1e30f; }  // iou -> 0
            float parea = (px2 - px1) * (py2 - py1);
            int best = (ch == 0) ? 0 : (act ? s_ce[off] : 0);
#pragma unroll
            for (int i = 0; i < 4; i++) {
                float iou = iou_bp(bb[i], ba[i], px1, py1, px2, py2, parea);
                int hb = __float_as_int(iou) & 0xFFFFFFF0;
                best = max(best, hb | (ch * 4 + i));                          // per-prior argmax
                bbest[i] = max(bbest[i], (unsigned)hb | (unsigned)(15 - it)); // per-box best
            }
            if (act) s_ce[off] = best;
        }
#pragma unroll
        for (int i = 0; i < 4; i++) {
            int itw = 15 - (int)(bbest[i] & 15u);
            int pw  = itw * THREADS + tid;
            if (pw >= NP) pw = NP - 1;   // only reachable with value bits 0
            unsigned long long key =
                ((unsigned long long)(bbest[i] & 0xFFFFFFF0u) << 32) | (unsigned)(NP - 1 - pw);
            atomicMax(&s_best[ch * 4 + i], key);
        }
    }
    __syncthreads();

    // ---- forced matching: sequential last-write-wins (XLA scatter semantics) ----
    if (tid == 0) {
        for (int m = 0; m < NM; m++) {
            int pp = NP - 1 - (int)(unsigned)(s_best[m] & 0xFFFFFFFFull);
            s_ce[pp] = 0x3F800000 | m;   // ov = 1.0, obj = m
        }
    }
    __syncthreads();

    // ---- pass 2: CE + positives (L1/conf) + fused top-byte histogram ----
    {
        float l1a = 0.f, cpa = 0.f; int npa = 0;
#pragma unroll 1
        for (int it = 0; it < NIT; it++) {
            int off = it * THREADS + tid;
            bool act = off < NP;
            float ce_neg = 0.f;
            if (act) {
                int key = s_ce[off];
                int bm  = key & 15;
                int cls = (key >= THRESH_BITS) ? s_lab[bm] : 0;
                float2 sc = sc2[off];
                float ce = ce_from_scores(sc, cls);
                ce_neg = ce;
                if (cls) {
                    npa++; cpa += ce;
                    l1a += l1_term(s_bx4[bm], prior4[off], pl4[off]);
                    ce_neg = 0.f;
                }
                s_ce[off] = __float_as_int(ce_neg);
            }
            unsigned byte = act ? (__float_as_uint(ce_neg) >> 24)
                                : (0x100u + (unsigned)lane);
            unsigned peers = __match_any_sync(0xffffffffu, byte);
            if (act && (int)(__ffs(peers) - 1) == lane)
                atomicAdd(&s_hist[byte], (unsigned)__popc(peers));
        }
        l1a = warp_sum(l1a); cpa = warp_sum(cpa);
        float npf = warp_sum((float)npa);
        if (lane == 0) { s_wl1[wid] = l1a; s_wcp[wid] = cpa; s_wnp[wid] = (int)npf; }
    }
    __syncthreads();
    if (tid == 0) {
        float a = 0.f, b = 0.f; int c = 0;
        for (int w = 0; w < 32; w++) { a += s_wl1[w]; b += s_wcp[w]; c += s_wnp[w]; }
        s_l1 = a; s_conf = b; s_npos = c;
    }
    __syncthreads();

    const int npos = s_npos;
    int K = 3 * npos; if (K > NP) K = NP;

    // ---- radix select: exact sum of top-K of ce_neg (level 0 already built) ----
    if (K > 0) {
        if (tid == 0) { s_pref = 0u; s_kk = K; }
        __syncthreads();
        select_scan(s_hist, &s_pref, &s_kk, 0u, 24, lane, tid);
        __syncthreads();
#pragma unroll 1
        for (int pass = 2; pass >= 0; pass--) {
            const int shift = pass * 8;
            if (tid < 256) s_hist[tid] = 0u;
            __syncthreads();
            const unsigned pref   = s_pref;
            const unsigned maskHi = 0xFFFFFFFFu << (shift + 8);
#pragma unroll 1
            for (int it = 0; it < NIT; it++) {
                int off = it * THREADS + tid;
                bool predt = false; unsigned bin = 0x100u + (unsigned)lane;
                if (off < NP) {
                    unsigned kb = (unsigned)s_ce[off];
                    if ((kb & maskHi) == pref) { predt = true; bin = (kb >> shift) & 0xFF; }
                }
                unsigned peers = __match_any_sync(0xffffffffu, bin);
                if (predt && (int)(__ffs(peers) - 1) == lane)
                    atomicAdd(&s_hist[bin], (unsigned)__popc(peers));
            }
            __syncthreads();
            select_scan(s_hist, &s_pref, &s_kk, pref, shift, lane, tid);
            __syncthreads();
        }
        const unsigned T = s_pref;
        float sgt = 0.f;
#pragma unroll 1
        for (int it = 0; it < NIT; it++) {
            int off = it * THREADS + tid;
            if (off < NP) {
                unsigned kb = (unsigned)s_ce[off];
                if (kb > T) sgt += __uint_as_float(kb);
            }
        }
        sgt = warp_sum(sgt);
        if (lane == 0) atomicAdd(&s_sumgt, sgt);
        __syncthreads();
    }

    // ---- row outputs + last-block finalize ----
    if (tid == 0) {
        float conf_hard = (K > 0) ? (s_sumgt + (float)s_kk * __uint_as_float(s_pref)) : 0.f;
        g_rconf[row] = s_conf + conf_hard;
        g_rl1[row]   = s_l1;
        g_rnp[row]   = (float)npos;
        __threadfence();
        int t = atomicAdd(&g_counter, 1);
        s_fin = (t == NROWS - 1);
    }
    __syncthreads();
    if (s_fin && tid < 32) {
        __threadfence();
        float v = 0.f;
        if (tid < NC) {
            volatile float* vc = g_rconf;
            volatile float* vl = g_rl1;
            volatile float* vn = g_rnp;
            float conf = 0.f, l1 = 0.f, np = 0.f;
#pragma unroll
            for (int n = 0; n < NB; n++) {
                int r = n * NC + tid;
                conf += vc[r]; l1 += vl[r]; np += vn[r];
            }
            if (np > 0.f)
                v = (conf + l1 / fmaxf(np * 4.f, 1.f)) / fmaxf(np, 1.f);
        }
        v = warp_sum(v);
        if (tid == 0) { out[0] = v / (float)NC; g_counter = 0; }
    }
}

extern "C" void kernel_launch(void* const* d_in, const int* in_sizes, int n_in,
                              void* d_out, int out_size) {
    const float* ploc   = (const float*)d_in[0];
    const float* pscore = (const float*)d_in[1];
    const float* boxes  = (const float*)d_in[2];
    const int*   labels = (const int*)d_in[3];
    const float* priors = (const float*)d_in[4];
    float* out = (float*)d_out;

    mb_all<<<NROWS, THREADS>>>(ploc, pscore, boxes, labels, priors, out);
}